// round 17
// baseline (speedup 1.0000x reference)
#include <cuda_runtime.h>
#include <cuda_bf16.h>
#include <cstdint>
#include <cstddef>

// ---------------------------------------------------------------------------
// Problem constants
// ---------------------------------------------------------------------------
#define GH 6
#define GM 512          // batch
#define GN 1000         // classes
#define GNP 1024        // padded classes
#define GK 2048         // feature dim
#define TAUC 0.5f
#define NTILES_N 8      // GNP / BN

// GEMM tiling (proven config: BK=64, 2-stage)
#define BM 64
#define BN 128
#define BK 64                     // bf16 elems per stage (128 B rows)
#define NKB (GK / BK)             // 32 stages
#define A_TILE_B (BM * 128)       // 8192 B per A split tile
#define B_TILE_B (BN * 128)       // 16384 B per B split tile
#define STAGE_B (2 * A_TILE_B + 2 * B_TILE_B)   // 49152 B
#define SMEM_DYN (2 * STAGE_B + 1024)

#define NFBLK 1536                // convert: feats blocks (4 float4 per thread)
#define NWBLK 3072                // convert: W blocks (16 c-tiles x 32 k-tiles x 6 h)

// ---------------------------------------------------------------------------
// Device-global scratch (no allocation allowed)
// ---------------------------------------------------------------------------
__device__ __align__(16) __nv_bfloat16 g_fa0[GH * GM * GK];
__device__ __align__(16) __nv_bfloat16 g_fa1[GH * GM * GK];
__device__ __align__(16) __nv_bfloat16 g_wt0[GH * GNP * GK];
__device__ __align__(16) __nv_bfloat16 g_wt1[GH * GNP * GK];
__device__ float g_logits[GH * GM * GN];
__device__ __align__(16) float g_pmax[GH * GM * NTILES_N];
__device__ __align__(16) float g_psum[GH * GM * NTILES_N];
__device__ __align__(16) int   g_pidx[GH * GM * NTILES_N];

// ---------------------------------------------------------------------------
// Helpers (baseline PTX only — safe on plain sm_103 target)
// ---------------------------------------------------------------------------
__device__ __forceinline__ uint32_t smem_to_u32(const void* p) {
    uint32_t a;
    asm("{ .reg .u64 t; cvta.to.shared.u64 t, %1; cvt.u32.u64 %0, t; }"
        : "=r"(a) : "l"(p));
    return a;
}

__device__ __forceinline__ void cp16(uint32_t s, const void* g) {
    asm volatile("cp.async.cg.shared.global [%0], [%1], 16;\n" :: "r"(s), "l"(g));
}
#define CP_COMMIT() asm volatile("cp.async.commit_group;\n" ::: "memory")
#define CP_WAIT1()  asm volatile("cp.async.wait_group 1;\n" ::: "memory")
#define CP_WAIT0()  asm volatile("cp.async.wait_group 0;\n" ::: "memory")

__device__ __forceinline__ void ldmx4(uint32_t* r, uint32_t addr) {
    asm volatile("ldmatrix.sync.aligned.m8n8.x4.shared.b16 {%0,%1,%2,%3}, [%4];"
                 : "=r"(r[0]), "=r"(r[1]), "=r"(r[2]), "=r"(r[3]) : "r"(addr));
}

__device__ __forceinline__ void mma16816(float* c, const uint32_t* a, const uint32_t* b) {
    asm volatile(
        "mma.sync.aligned.m16n8k16.row.col.f32.bf16.bf16.f32 "
        "{%0,%1,%2,%3}, {%4,%5,%6,%7}, {%8,%9}, {%0,%1,%2,%3};"
        : "+f"(c[0]), "+f"(c[1]), "+f"(c[2]), "+f"(c[3])
        : "r"(a[0]), "r"(a[1]), "r"(a[2]), "r"(a[3]), "r"(b[0]), "r"(b[1]));
}

// swizzled byte offset within a tile: 128B rows, 16B chunks, xor-8
__device__ __forceinline__ uint32_t swz(int row, int ch) {
    return (uint32_t)(row * 128 + ((ch ^ (row & 7)) << 4));
}

__device__ __forceinline__ void split2(float v, __nv_bfloat16& s0, __nv_bfloat16& s1) {
    s0 = __float2bfloat16_rn(v);
    s1 = __float2bfloat16_rn(v - __bfloat162float(s0));
}

// Combine 8 tile partials for row (h, b): returns M (max), I (argmax), S (sumexp/expM)
__device__ __forceinline__ void combine_row(int h, int b, float& M, int& I, float& S)
{
    const size_t base = ((size_t)h * GM + b) * NTILES_N;
    float4 m0 = *reinterpret_cast<const float4*>(&g_pmax[base]);
    float4 m1 = *reinterpret_cast<const float4*>(&g_pmax[base + 4]);
    int4   i0 = *reinterpret_cast<const int4*>(&g_pidx[base]);
    int4   i1 = *reinterpret_cast<const int4*>(&g_pidx[base + 4]);
    float4 s0 = *reinterpret_cast<const float4*>(&g_psum[base]);
    float4 s1 = *reinterpret_cast<const float4*>(&g_psum[base + 4]);
    const float mv[8] = {m0.x, m0.y, m0.z, m0.w, m1.x, m1.y, m1.z, m1.w};
    const int   iv[8] = {i0.x, i0.y, i0.z, i0.w, i1.x, i1.y, i1.z, i1.w};
    const float sv[8] = {s0.x, s0.y, s0.z, s0.w, s1.x, s1.y, s1.z, s1.w};
    M = -1e30f; I = 0;
    #pragma unroll
    for (int j = 0; j < 8; j++)
        if (mv[j] > M) { M = mv[j]; I = iv[j]; }
    S = 0.0f;
    #pragma unroll
    for (int j = 0; j < 8; j++)
        S += sv[j] * expf(mv[j] - M);
}

__device__ __forceinline__ int route_from_conf(const float* conf)
{
    int   firstExit = -1;
    float bestc = -1e30f;
    int   besth = 0;
    #pragma unroll
    for (int h = 0; h < GH; h++) {
        const float c = conf[h];
        if (firstExit < 0 && c >= TAUC) firstExit = h;
        if (c > bestc) { bestc = c; besth = h; }
    }
    return (firstExit >= 0) ? firstExit : besth;
}

// ---------------------------------------------------------------------------
// Kernel A: merged converts.
//   blocks [0, NFBLK)          : feats fp32 -> 2 bf16 splits (4 float4/thread)
//   blocks [NFBLK, NFBLK+NWBLK): W transpose+split, 64k x 64c tiles
// ---------------------------------------------------------------------------
__global__ __launch_bounds__(256) void convert_all_kernel(
    const float* __restrict__ feats, const float* __restrict__ W)
{
    const int bid = blockIdx.x;
    if (bid < NFBLK) {
        const int base = bid * 256 + threadIdx.x;
        #pragma unroll
        for (int i = 0; i < 4; i++) {
            const int gid = base + i * (NFBLK * 256);
            float4 v = reinterpret_cast<const float4*>(feats)[gid];
            __nv_bfloat16 a0[4], a1[4];
            split2(v.x, a0[0], a1[0]);
            split2(v.y, a0[1], a1[1]);
            split2(v.z, a0[2], a1[2]);
            split2(v.w, a0[3], a1[3]);
            reinterpret_cast<uint2*>(g_fa0)[gid] = *reinterpret_cast<uint2*>(a0);
            reinterpret_cast<uint2*>(g_fa1)[gid] = *reinterpret_cast<uint2*>(a1);
        }
    } else {
        const int wb = bid - NFBLK;                // 0..3071
        const int h  = wb >> 9;                    // 512 blocks per head
        const int k0 = ((wb >> 4) & 31) * 64;
        const int c0 = (wb & 15) * 64;
        __shared__ float t[64][65];
        const int tid  = threadIdx.x;
        const int lane = tid & 31;
        const int wid  = tid >> 5;                 // 0..7

        #pragma unroll
        for (int it = 0; it < 8; it++) {
            const int r = it * 8 + wid;            // local k
            #pragma unroll
            for (int half = 0; half < 2; half++) {
                const int c = c0 + half * 32 + lane;
                t[r][half * 32 + lane] =
                    (c < GN) ? W[((size_t)h * GK + (k0 + r)) * GN + c] : 0.0f;
            }
        }
        __syncthreads();

        #pragma unroll
        for (int p = 0; p < 8; p++) {
            const int cl = p * 8 + wid;            // local c 0..63
            const int cg = c0 + cl;
            float v0 = t[2 * lane][cl];
            float v1 = t[2 * lane + 1][cl];
            __nv_bfloat16 a0, a1, b0, b1;
            split2(v0, a0, a1);
            split2(v1, b0, b1);
            __nv_bfloat162 p0, p1;
            p0.x = a0; p0.y = b0;
            p1.x = a1; p1.y = b1;
            size_t widx = (((size_t)h * GNP + cg) * GK + k0 + 2 * lane) >> 1;
            reinterpret_cast<uint32_t*>(g_wt0)[widx] = *reinterpret_cast<uint32_t*>(&p0);
            reinterpret_cast<uint32_t*>(g_wt1)[widx] = *reinterpret_cast<uint32_t*>(&p1);
        }
    }
}

// ---------------------------------------------------------------------------
// Kernel B: mma.sync bf16 GEMM (3-product fp32 emulation) +
//           fused bias + per-tile softmax partial stats in the epilogue.
// ---------------------------------------------------------------------------
__device__ __forceinline__ void load_stage(
    uint32_t sb, int kb, int tid,
    const __nv_bfloat16* const* srcs)
{
    #pragma unroll
    for (int i = 0; i < 2; i++)
        #pragma unroll
        for (int it = 0; it < 2; it++) {
            const int q   = it * 256 + tid;
            const int row = q >> 3;
            const int ch  = q & 7;
            const __nv_bfloat16* g = srcs[i] + (size_t)row * GK + kb * BK + ch * 8;
            cp16(sb + i * A_TILE_B + swz(row, ch), g);
        }
    #pragma unroll
    for (int i = 0; i < 2; i++)
        #pragma unroll
        for (int it = 0; it < 4; it++) {
            const int q   = it * 256 + tid;
            const int row = q >> 3;
            const int ch  = q & 7;
            const __nv_bfloat16* g = srcs[2 + i] + (size_t)row * GK + kb * BK + ch * 8;
            cp16(sb + 2 * A_TILE_B + i * B_TILE_B + swz(row, ch), g);
        }
}

__global__ __launch_bounds__(256, 2) void sdn_mma_gemm(const float* __restrict__ bias)
{
    extern __shared__ char smem[];
    const uint32_t sm0 = (smem_to_u32(smem) + 1023u) & ~1023u;

    __shared__ float s_pm[2][32][4];
    __shared__ float s_ps[2][32][4];
    __shared__ int   s_pi[2][32][4];

    const int tid  = threadIdx.x;
    const int wid  = tid >> 5;
    const int lane = tid & 31;
    const int wm   = (wid & 1) * 32;        // 2 warps along m
    const int wn   = (wid >> 1) * 32;       // 4 warps along n
    const int wmg  = wid & 1;
    const int wnid = wid >> 1;

    const int h  = blockIdx.z;
    const int m0 = blockIdx.y * BM;
    const int n0 = blockIdx.x * BN;

    const __nv_bfloat16* srcs[4] = {
        g_fa0 + ((size_t)h * GM  + m0) * GK,
        g_fa1 + ((size_t)h * GM  + m0) * GK,
        g_wt0 + ((size_t)h * GNP + n0) * GK,
        g_wt1 + ((size_t)h * GNP + n0) * GK
    };

    float acc[2][4][4];
    #pragma unroll
    for (int f = 0; f < 2; f++)
        #pragma unroll
        for (int n = 0; n < 4; n++)
            #pragma unroll
            for (int e = 0; e < 4; e++) acc[f][n][e] = 0.0f;

    // Prologue
    load_stage(sm0, 0, tid, srcs);
    CP_COMMIT();

    #pragma unroll 1
    for (int kb = 0; kb < NKB; kb++) {
        const int cur = kb & 1;
        if (kb + 1 < NKB) {
            load_stage(sm0 + (cur ^ 1) * STAGE_B, kb + 1, tid, srcs);
            CP_COMMIT();
            CP_WAIT1();
        } else {
            CP_WAIT0();
        }
        __syncthreads();

        const uint32_t sb = sm0 + cur * STAGE_B;
        #pragma unroll
        for (int ks = 0; ks < 4; ks++) {
            uint32_t ra[2][2][4];
            #pragma unroll
            for (int s = 0; s < 2; s++)
                #pragma unroll
                for (int f = 0; f < 2; f++) {
                    int row = wm + f * 16 + (lane & 15);
                    int ch  = 2 * ks + (lane >> 4);
                    ldmx4(ra[s][f], sb + s * A_TILE_B + swz(row, ch));
                }
            uint32_t rb[2][2][4];
            #pragma unroll
            for (int s = 0; s < 2; s++)
                #pragma unroll
                for (int g = 0; g < 2; g++) {
                    int row = wn + g * 16 + (lane & 7) + ((lane >> 4) << 3);
                    int ch  = 2 * ks + ((lane >> 3) & 1);
                    ldmx4(rb[s][g], sb + 2 * A_TILE_B + s * B_TILE_B + swz(row, ch));
                }
            const int PA[3] = {0, 0, 1};
            const int PB[3] = {0, 1, 0};
            #pragma unroll
            for (int p = 0; p < 3; p++)
                #pragma unroll
                for (int f = 0; f < 2; f++)
                    #pragma unroll
                    for (int g = 0; g < 2; g++)
                        #pragma unroll
                        for (int h2 = 0; h2 < 2; h2++)
                            mma16816(acc[f][g * 2 + h2],
                                     ra[PA[p]][f], &rb[PB[p]][g][h2 * 2]);
        }
        __syncthreads();
    }

    // Epilogue: bias + store logits + per-row partial stats (max/argmax/sumexp)
    const int g8  = lane >> 2;
    const int tig = lane & 3;
    #pragma unroll
    for (int f = 0; f < 2; f++) {
        #pragma unroll
        for (int rr = 0; rr < 2; rr++) {
            const int mrow = m0 + wm + f * 16 + rr * 8 + g8;
            float* orow = g_logits + ((size_t)h * GM + mrow) * GN;
            float vv[8];
            float vmax = -1e30f;
            int   vidx = 0;
            #pragma unroll
            for (int nf = 0; nf < 4; nf++) {
                const int ncol = n0 + wn + nf * 8 + tig * 2;
                float v0 = acc[f][nf][rr * 2 + 0];
                float v1 = acc[f][nf][rr * 2 + 1];
                if (ncol + 1 < GN) {
                    v0 += bias[h * GN + ncol];
                    v1 += bias[h * GN + ncol + 1];
                    *reinterpret_cast<float2*>(orow + ncol) = make_float2(v0, v1);
                } else if (ncol < GN) {
                    v0 += bias[h * GN + ncol];
                    orow[ncol] = v0;
                    v1 = -1e30f;
                } else {
                    v0 = -1e30f; v1 = -1e30f;
                }
                vv[nf * 2 + 0] = v0;
                vv[nf * 2 + 1] = v1;
                if (v0 > vmax) { vmax = v0; vidx = ncol; }
                if (v1 > vmax) { vmax = v1; vidx = ncol + 1; }
            }
            #pragma unroll
            for (int msk = 1; msk <= 2; msk <<= 1) {
                float om = __shfl_xor_sync(0xffffffffu, vmax, msk);
                int   oi = __shfl_xor_sync(0xffffffffu, vidx, msk);
                if (om > vmax || (om == vmax && oi < vidx)) { vmax = om; vidx = oi; }
            }
            float s = 0.0f;
            #pragma unroll
            for (int i = 0; i < 8; i++) s += expf(vv[i] - vmax);
            s += __shfl_xor_sync(0xffffffffu, s, 1);
            s += __shfl_xor_sync(0xffffffffu, s, 2);
            if (tig == 0) {
                const int rl = f * 16 + rr * 8 + g8;
                s_pm[wmg][rl][wnid] = vmax;
                s_ps[wmg][rl][wnid] = s;
                s_pi[wmg][rl][wnid] = vidx;
            }
        }
    }
    __syncthreads();

    if (tid < 64) {
        const int g2 = tid >> 5;
        const int rl = tid & 31;
        float M = -1e30f; int I = 0;
        #pragma unroll
        for (int j = 0; j < 4; j++) {
            float m = s_pm[g2][rl][j];
            if (m > M) { M = m; I = s_pi[g2][rl][j]; }
        }
        float S = 0.0f;
        #pragma unroll
        for (int j = 0; j < 4; j++)
            S += s_ps[g2][rl][j] * expf(s_pm[g2][rl][j] - M);
        const int mrow = m0 + g2 * 32 + rl;
        const size_t pr = ((size_t)h * GM + mrow) * NTILES_N + blockIdx.x;
        g_pmax[pr] = M;
        g_psum[pr] = S;
        g_pidx[pr] = I;
    }
}

// ---------------------------------------------------------------------------
// Kernel C: fused tail — route + gather + loss/acc/exit in ONE launch.
//   blocks 0..GM-1 : row b — in-block route, copy routed logits row to out
//   block  GM      : loss/acc/exit_idx outputs (256 threads x 2 rows)
// ---------------------------------------------------------------------------
__global__ __launch_bounds__(256) void sdn_tail_kernel(
    const int* __restrict__ y_true, float* __restrict__ out)
{
    const int blk = blockIdx.x;
    if (blk < GM) {
        const int b = blk;
        __shared__ float s_conf[GH];
        __shared__ int   s_ex;
        if (threadIdx.x < GH) {
            float M, S; int I;
            combine_row(threadIdx.x, b, M, I, S);
            s_conf[threadIdx.x] = 1.0f / S;
        }
        __syncthreads();
        if (threadIdx.x == 0) s_ex = route_from_conf(s_conf);
        __syncthreads();
        const int ex = s_ex;
        const float4* src = reinterpret_cast<const float4*>(
            g_logits + ((size_t)ex * GM + b) * GN);
        float4* dst = reinterpret_cast<float4*>(out + (size_t)b * GN);
        if (threadIdx.x < 250) dst[threadIdx.x] = src[threadIdx.x];
    } else {
        // loss / acc / exit outputs
        float lsum = 0.0f, asum = 0.0f;
        #pragma unroll
        for (int half = 0; half < 2; half++) {
            const int b = threadIdx.x + half * 256;
            float conf[GH], lse[GH];
            int   amax[GH];
            #pragma unroll
            for (int h = 0; h < GH; h++) {
                float M, S; int I;
                combine_row(h, b, M, I, S);
                lse[h]  = M + logf(S);
                conf[h] = 1.0f / S;
                amax[h] = I;
            }
            const int ex = route_from_conf(conf);
            out[GM * GN + b] = (float)ex;
            const int y = y_true[b];
            const float logit_y = g_logits[((size_t)ex * GM + b) * GN + y];
            lsum += -(logit_y - lse[ex]);
            asum += (amax[ex] == y) ? 1.0f : 0.0f;
        }
        __shared__ float sl[256];
        __shared__ float sa[256];
        sl[threadIdx.x] = lsum; sa[threadIdx.x] = asum;
        __syncthreads();
        for (int s = 128; s > 0; s >>= 1) {
            if (threadIdx.x < s) {
                sl[threadIdx.x] += sl[threadIdx.x + s];
                sa[threadIdx.x] += sa[threadIdx.x + s];
            }
            __syncthreads();
        }
        if (threadIdx.x == 0) {
            out[GM * GN + GM + 0] = sl[0] / (float)GM;
            out[GM * GN + GM + 1] = sa[0] / (float)GM;
        }
    }
}

// ---------------------------------------------------------------------------
extern "C" void kernel_launch(void* const* d_in, const int* in_sizes, int n_in,
                              void* d_out, int out_size)
{
    const float* feats = (const float*)d_in[0];  // [6,512,2048]
    const float* W     = (const float*)d_in[1];  // [6,2048,1000]
    const float* bias  = (const float*)d_in[2];  // [6,1000]
    const int*   y     = (const int*)  d_in[3];  // [512]
    float* out = (float*)d_out;

    cudaFuncSetAttribute(sdn_mma_gemm, cudaFuncAttributeMaxDynamicSharedMemorySize, SMEM_DYN);

    convert_all_kernel<<<NFBLK + NWBLK, 256>>>(feats, W);
    sdn_mma_gemm<<<dim3(GNP / BN, GM / BM, GH), 256, SMEM_DYN>>>(bias);
    sdn_tail_kernel<<<GM + 1, 256>>>(y, out);
}